// round 3
// baseline (speedup 1.0000x reference)
#include <cuda_runtime.h>
#include <cuda_bf16.h>
#include <cstdint>

// ---------------------------------------------------------------------------
// Problem constants
// ---------------------------------------------------------------------------
#define BB 16
#define TT 1024
#define FIN 128
#define HH 256
#define G4 1024            // 4*H
#define MM (BB*TT)         // 16384

typedef unsigned long long ull;

// ---------------------------------------------------------------------------
// Scratch (static device arrays; no dynamic allocation allowed)
// ---------------------------------------------------------------------------
__device__ float g_xg [MM * G4];      // gate preactivations (reused layer0/1)
__device__ float g_h1 [MM * HH];      // layer0 hidden sequence
__device__ float g_h2 [MM * HH];      // layer1 hidden sequence (lstm_out)
__device__ float g_Q  [MM * HH];
__device__ float g_K  [MM * HH];
__device__ float g_V  [MM * HH];
__device__ float g_S  [BB * TT * TT]; // attention scores / probs
__device__ float g_att[MM * HH];
__device__ float g_dump[4 * BB * HH]; // fallback sink for h_n/c_n

// ---------------------------------------------------------------------------
// Helpers
// ---------------------------------------------------------------------------
__device__ __forceinline__ uint32_t smem_u32(const void* p) {
    return (uint32_t)__cvta_generic_to_shared(p);
}
__device__ __forceinline__ void st_cluster_f32(uint32_t saddr, int dst_rank, float v) {
    uint32_t r;
    asm volatile("mapa.shared::cluster.u32 %0, %1, %2;" : "=r"(r) : "r"(saddr), "r"(dst_rank));
    asm volatile("st.shared::cluster.f32 [%0], %1;" :: "r"(r), "f"(v) : "memory");
}
__device__ __forceinline__ void cluster_sync_all() {
    asm volatile("barrier.cluster.arrive.aligned;" ::: "memory");
    asm volatile("barrier.cluster.wait.aligned;" ::: "memory");
}
__device__ __forceinline__ float fast_sigmoid(float x) {
    return 1.f / (1.f + __expf(-x));
}
__device__ __forceinline__ float fast_tanh(float x) {
    x = fminf(fmaxf(x, -15.f), 15.f);
    float e = __expf(2.f * x);
    return (e - 1.f) / (e + 1.f);
}

// packed fp32x2 fma: d.lo += a.lo*b.lo ; d.hi += a.hi*b.hi
__device__ __forceinline__ void ffma2(ull& d, ull a, ull b) {
    asm("fma.rn.f32x2 %0, %1, %2, %0;" : "+l"(d) : "l"(a), "l"(b));
}
__device__ __forceinline__ ull dup2(float x) {
    ull r;
    asm("mov.b64 %0, {%1, %1};" : "=l"(r) : "f"(x));
    return r;
}
__device__ __forceinline__ void unpack2(ull v, float& lo, float& hi) {
    asm("mov.b64 {%0, %1}, %2;" : "=f"(lo), "=f"(hi) : "l"(v));
}

// cluster-scope mbarrier ops
__device__ __forceinline__ void mbar_init(uint32_t addr, uint32_t count) {
    asm volatile("mbarrier.init.shared.b64 [%0], %1;" :: "r"(addr), "r"(count) : "memory");
}
__device__ __forceinline__ void mbar_arrive_remote(uint32_t addr, uint32_t dst_rank) {
    asm volatile(
        "{\n\t"
        ".reg .b32 ra;\n\t"
        "mapa.shared::cluster.u32 ra, %0, %1;\n\t"
        "mbarrier.arrive.release.cluster.shared::cluster.b64 _, [ra];\n\t"
        "}"
        :: "r"(addr), "r"(dst_rank) : "memory");
}
__device__ __forceinline__ void mbar_wait_cluster(uint32_t addr, uint32_t parity) {
    asm volatile(
        "{\n\t"
        ".reg .pred P;\n\t"
        "WL_%=:\n\t"
        "mbarrier.try_wait.parity.acquire.cluster.shared::cta.b64 P, [%0], %1, 0x989680;\n\t"
        "@P bra.uni WD_%=;\n\t"
        "bra.uni WL_%=;\n\t"
        "WD_%=:\n\t"
        "}"
        :: "r"(addr), "r"(parity) : "memory");
}

// ---------------------------------------------------------------------------
// Persistent LSTM recurrence kernel.
// 16 clusters (batches) x 8 CTAs. Each CTA owns 32 hidden dims; Whh slice
// (128x256 fp32 = 128KB) lives in registers as f32x2 pairs. Thread t:
// u=t>>3 -> outputs o=4u..4u+3 (same gate), kc=t&7 -> k-pairs {2kc+16j,+1}.
// GEMV: 64 FFMA2/thread; 8-lane shfl reduce. h broadcast to all 8 peer CTAs
// via DSMEM (double buffered); per-step sync via one cluster mbarrier with
// 8 arrivals (arrive.release.cluster / try_wait.acquire.cluster).
// Safety: a CTA arrives only after __syncthreads, i.e. after ALL its warps
// finished reading buffer rb, so writing rb again next step is race-free.
// ---------------------------------------------------------------------------
__global__ void __cluster_dims__(8, 1, 1) __launch_bounds__(256, 1)
lstm_rec_kernel(const float* __restrict__ xg, const float* __restrict__ Whh,
                float* __restrict__ hseq, float* __restrict__ hn, float* __restrict__ cn)
{
    __shared__ float h_all[2][HH];
    __shared__ float gates_s[128];
    __shared__ __align__(8) ull mbar[1];

    const int tid   = threadIdx.x;
    const int rank  = blockIdx.x & 7;
    const int batch = blockIdx.x >> 3;
    const int u     = tid >> 3;   // 0..31 : output group (4 outputs, same gate)
    const int kc    = tid & 7;    // 0..7  : k-pair subset
    const int o0    = 4 * u;      // local output base (gate = o0>>5, hid = o0&31..+3)

    // ---- load Whh slice into registers as f32x2 k-pairs ----
    ull w2[4][16];
    #pragma unroll
    for (int oo = 0; oo < 4; oo++) {
        const int o   = o0 + oo;
        const int row = ((o >> 5) << 8) + 32 * rank + (o & 31);
        const float* wr = Whh + (long)row * HH;
        #pragma unroll
        for (int j = 0; j < 16; j++) {
            float2 wp = *(const float2*)(wr + 2 * kc + 16 * j);
            ull v;
            asm("mov.b64 %0, {%1, %2};" : "=l"(v) : "f"(wp.x), "f"(wp.y));
            w2[oo][j] = v;
        }
    }

    h_all[0][tid] = 0.f;
    if (tid == 0) mbar_init(smem_u32(mbar), 8);

    float c_state = 0.f;
    uint32_t haddr[2] = {0, 0};
    if (tid < 32) {
        haddr[0] = smem_u32(&h_all[0][32 * rank + tid]);
        haddr[1] = smem_u32(&h_all[1][32 * rank + tid]);
    }
    const uint32_t mb = smem_u32(mbar);
    __syncthreads();
    cluster_sync_all();   // mbarrier + h0 visible cluster-wide

    const long xg_base = (long)batch * TT * G4;
    const int  xg_col  = ((o0 >> 5) << 8) + 32 * rank + (o0 & 31); // 4 consecutive cols

    // prefetch xg for t=0
    float4 xgv = make_float4(0.f, 0.f, 0.f, 0.f);
    if (kc == 0) xgv = *(const float4*)(xg + xg_base + xg_col);

    for (int t = 0; t < TT; t++) {
        const int rb = t & 1;
        const int wb = rb ^ 1;

        // GEMV over h_all[rb] : 64 FFMA2
        ull acc2[4] = {0ull, 0ull, 0ull, 0ull};
        const float* hrow = h_all[rb];
        #pragma unroll
        for (int j = 0; j < 16; j++) {
            ull h2 = *(const ull*)(hrow + 2 * kc + 16 * j);
            ffma2(acc2[0], w2[0][j], h2);
            ffma2(acc2[1], w2[1][j], h2);
            ffma2(acc2[2], w2[2][j], h2);
            ffma2(acc2[3], w2[3][j], h2);
        }
        float acc[4];
        #pragma unroll
        for (int g = 0; g < 4; g++) {
            float lo, hi;
            unpack2(acc2[g], lo, hi);
            acc[g] = lo + hi;
        }
        #pragma unroll
        for (int off = 4; off >= 1; off >>= 1) {
            acc[0] += __shfl_xor_sync(0xffffffffu, acc[0], off);
            acc[1] += __shfl_xor_sync(0xffffffffu, acc[1], off);
            acc[2] += __shfl_xor_sync(0xffffffffu, acc[2], off);
            acc[3] += __shfl_xor_sync(0xffffffffu, acc[3], off);
        }
        if (kc == 0) {
            *(float4*)&gates_s[o0] =
                make_float4(acc[0] + xgv.x, acc[1] + xgv.y, acc[2] + xgv.z, acc[3] + xgv.w);
        }
        __syncthreads();   // all warps done reading h_all[rb]; gates_s ready

        if (tid < 32) {    // warp 0 = writer warp
            const int hid = tid;
            float gi = gates_s[hid];
            float gf = gates_s[32 + hid];
            float gg = gates_s[64 + hid];
            float go = gates_s[96 + hid];
            float ig = fast_sigmoid(gi);
            float fg = fast_sigmoid(gf);
            float gt = fast_tanh(gg);
            float og = fast_sigmoid(go);
            c_state = fg * c_state + ig * gt;
            float h = og * fast_tanh(c_state);
            hseq[((long)batch * TT + t) * HH + 32 * rank + hid] = h;
            uint32_t dst = haddr[wb];
            #pragma unroll
            for (int d = 0; d < 8; d++) st_cluster_f32(dst, d, h);
            if (t == TT - 1) {
                hn[batch * HH + 32 * rank + hid] = h;
                cn[batch * HH + 32 * rank + hid] = c_state;
            }
            __syncwarp(0xffffffffu);   // all lanes' DSMEM stores done
            if (tid < 8) mbar_arrive_remote(mb, (uint32_t)tid);  // release-cluster
        }

        // prefetch next xg row (independent of the barrier)
        if (kc == 0 && t + 1 < TT) {
            xgv = *(const float4*)(xg + xg_base + (long)(t + 1) * G4 + xg_col);
        }

        // wait for all 8 CTAs' h writes of this step (phase t)
        mbar_wait_cluster(mb, (uint32_t)(t & 1));
    }
}

// ---------------------------------------------------------------------------
// Pipelined SGEMM with packed f32x2 FMA.
// C[M,N] = A[M,K] @ B^T (b_nt=1, B is [N,K]) or A @ B (b_nt=0, B is [K,N])
// + optional bias1[n] + bias2[n] + residual[m,n]. Batched via gridDim.z.
// Tiles 128x128x16, 256 threads, 8x8 microtiles (acc packed in f32x2 pairs
// along n). Register double-buffer: LDG for tile k+1 issued before compute.
// Smem layouts: As[k][m], Bs[k][n] (transposed on store; NN B is direct).
// ---------------------------------------------------------------------------
#define BKP 136

__global__ __launch_bounds__(256) void sgemm_kernel(
    const float* __restrict__ A, const float* __restrict__ B, float* __restrict__ C,
    int M, int N, int K,
    long sA, long sB, long sC,
    const float* __restrict__ bias1, const float* __restrict__ bias2,
    const float* __restrict__ res,
    int b_nt)
{
    __shared__ float As[16][BKP];
    __shared__ float Bs[16][BKP];

    const int bz = blockIdx.z;
    A += (long)bz * sA;
    B += (long)bz * sB;
    C += (long)bz * sC;

    const int bm = blockIdx.y * 128;
    const int bn = blockIdx.x * 128;
    const int tid = threadIdx.x;
    const int tx = tid & 15;
    const int ty = tid >> 4;

    // loader indices
    const int mA  = tid >> 1;        // 0..127 (row for A / NT-B)
    const int kA  = (tid & 1) * 8;   // 0 or 8
    const int kB2 = tid >> 4;        // 0..15  (NN B)
    const int nB2 = (tid & 15) * 8;  // 0..120

    const float* Aptr   = A + (long)(bm + mA) * K + kA;
    const float* BptrNT = B + (long)(bn + mA) * K + kA;
    const float* BptrNN = B + (long)kB2 * N + bn + nB2;

    ull acc2[8][4];
    #pragma unroll
    for (int i = 0; i < 8; i++)
        #pragma unroll
        for (int j = 0; j < 4; j++) acc2[i][j] = 0ull;

    // prefetch tile 0
    float4 pa0 = *(const float4*)(Aptr + 0);
    float4 pa1 = *(const float4*)(Aptr + 4);
    float4 pb0, pb1;
    if (b_nt) { pb0 = *(const float4*)(BptrNT + 0); pb1 = *(const float4*)(BptrNT + 4); }
    else      { pb0 = *(const float4*)(BptrNN + 0); pb1 = *(const float4*)(BptrNN + 4); }

    const int KT = K >> 4;
    for (int kt = 0; kt < KT; kt++) {
        // store current tile to smem (A transposed to [k][m])
        As[kA + 0][mA] = pa0.x; As[kA + 1][mA] = pa0.y;
        As[kA + 2][mA] = pa0.z; As[kA + 3][mA] = pa0.w;
        As[kA + 4][mA] = pa1.x; As[kA + 5][mA] = pa1.y;
        As[kA + 6][mA] = pa1.z; As[kA + 7][mA] = pa1.w;
        if (b_nt) {
            Bs[kA + 0][mA] = pb0.x; Bs[kA + 1][mA] = pb0.y;
            Bs[kA + 2][mA] = pb0.z; Bs[kA + 3][mA] = pb0.w;
            Bs[kA + 4][mA] = pb1.x; Bs[kA + 5][mA] = pb1.y;
            Bs[kA + 6][mA] = pb1.z; Bs[kA + 7][mA] = pb1.w;
        } else {
            *(float4*)&Bs[kB2][nB2]     = pb0;
            *(float4*)&Bs[kB2][nB2 + 4] = pb1;
        }
        __syncthreads();

        // prefetch next tile (hidden under compute)
        if (kt + 1 < KT) {
            const float* Ap = Aptr + (kt + 1) * 16;
            pa0 = *(const float4*)(Ap + 0);
            pa1 = *(const float4*)(Ap + 4);
            if (b_nt) {
                const float* Bp = BptrNT + (kt + 1) * 16;
                pb0 = *(const float4*)(Bp + 0);
                pb1 = *(const float4*)(Bp + 4);
            } else {
                const float* Bp = BptrNN + (long)(kt + 1) * 16 * N;
                pb0 = *(const float4*)(Bp + 0);
                pb1 = *(const float4*)(Bp + 4);
            }
        }

        // compute: per kk, 4 LDS.64 for b-pairs, 8 broadcast a + dup, 32 FFMA2
        #pragma unroll
        for (int kk = 0; kk < 16; kk++) {
            ull b2[4];
            b2[0] = *(const ull*)&Bs[kk][4 * tx];
            b2[1] = *(const ull*)&Bs[kk][4 * tx + 2];
            b2[2] = *(const ull*)&Bs[kk][64 + 4 * tx];
            b2[3] = *(const ull*)&Bs[kk][64 + 4 * tx + 2];
            #pragma unroll
            for (int i = 0; i < 8; i++) {
                float av = As[kk][(i < 4) ? (ty * 4 + i) : (64 + ty * 4 + (i - 4))];
                ull a2 = dup2(av);
                ffma2(acc2[i][0], a2, b2[0]);
                ffma2(acc2[i][1], a2, b2[1]);
                ffma2(acc2[i][2], a2, b2[2]);
                ffma2(acc2[i][3], a2, b2[3]);
            }
        }
        __syncthreads();
    }

    // epilogue
    #pragma unroll
    for (int i = 0; i < 8; i++) {
        const int m = bm + ((i < 4) ? (ty * 4 + i) : (64 + ty * 4 + (i - 4)));
        #pragma unroll
        for (int jh = 0; jh < 2; jh++) {
            const int n = bn + jh * 64 + tx * 4;
            float4 v;
            unpack2(acc2[i][2 * jh],     v.x, v.y);
            unpack2(acc2[i][2 * jh + 1], v.z, v.w);
            if (bias1) {
                const float4 b1 = *(const float4*)(bias1 + n);
                v.x += b1.x; v.y += b1.y; v.z += b1.z; v.w += b1.w;
            }
            if (bias2) {
                const float4 b2v = *(const float4*)(bias2 + n);
                v.x += b2v.x; v.y += b2v.y; v.z += b2v.z; v.w += b2v.w;
            }
            if (res) {
                const float4 r = *(const float4*)(res + (long)m * N + n);
                v.x += r.x; v.y += r.y; v.z += r.z; v.w += r.w;
            }
            *(float4*)(C + (long)m * N + n) = v;
        }
    }
}

// ---------------------------------------------------------------------------
// Softmax with ARMA modulation. One block (256 thr) per (b,q) row of 1024.
// mod depends only on d=|q-k| and is non-trivial only for d<=3.
// ---------------------------------------------------------------------------
__global__ __launch_bounds__(256) void softmax_mod_kernel(
    float* __restrict__ S, const float* __restrict__ ar_w, const float* __restrict__ ma_w)
{
    __shared__ float red[8];
    const int row = blockIdx.x;          // b*1024 + q
    const int q = row & (TT - 1);
    float* Sr = S + (long)row * TT;

    const float m0 = ma_w[0], m1 = ma_w[1];
    const float a0 = ar_w[0], a1 = ar_w[1], a2 = ar_w[2];
    const float mod0 = __expf(m0 + m1);
    const float mod1 = __expf(a0 + m0 + m1);
    const float mod2 = __expf(a1 + m1);
    const float mod3 = __expf(a2);

    const int t = threadIdx.x;
    float v[4];
    float mx = -1e30f;
    #pragma unroll
    for (int i = 0; i < 4; i++) {
        int k = t + 256 * i;
        float s = Sr[k] * 0.0625f;   // 1/sqrt(256)
        int d = ::abs(q - k);
        float md = (d > 3) ? 1.f : (d == 0 ? mod0 : (d == 1 ? mod1 : (d == 2 ? mod2 : mod3)));
        v[i] = s * md;
        mx = fmaxf(mx, v[i]);
    }
    #pragma unroll
    for (int off = 16; off; off >>= 1) mx = fmaxf(mx, __shfl_xor_sync(~0u, mx, off));
    if ((t & 31) == 0) red[t >> 5] = mx;
    __syncthreads();
    mx = red[0];
    #pragma unroll
    for (int w = 1; w < 8; w++) mx = fmaxf(mx, red[w]);

    float sum = 0.f;
    #pragma unroll
    for (int i = 0; i < 4; i++) { v[i] = __expf(v[i] - mx); sum += v[i]; }
    #pragma unroll
    for (int off = 16; off; off >>= 1) sum += __shfl_xor_sync(~0u, sum, off);
    __syncthreads();
    if ((t & 31) == 0) red[t >> 5] = sum;
    __syncthreads();
    sum = 0.f;
    #pragma unroll
    for (int w = 0; w < 8; w++) sum += red[w];
    const float inv = 1.f / sum;
    #pragma unroll
    for (int i = 0; i < 4; i++) Sr[t + 256 * i] = v[i] * inv;
}

// ---------------------------------------------------------------------------
// Launch
// ---------------------------------------------------------------------------
extern "C" void kernel_launch(void* const* d_in, const int* in_sizes, int n_in,
                              void* d_out, int out_size)
{
    const float* x    = (const float*)d_in[0];
    const float* Wih0 = (const float*)d_in[1];
    const float* Whh0 = (const float*)d_in[2];
    const float* bih0 = (const float*)d_in[3];
    const float* bhh0 = (const float*)d_in[4];
    const float* Wih1 = (const float*)d_in[5];
    const float* Whh1 = (const float*)d_in[6];
    const float* bih1 = (const float*)d_in[7];
    const float* bhh1 = (const float*)d_in[8];
    const float* ar_w = (const float*)d_in[9];
    const float* ma_w = (const float*)d_in[10];
    const float* Wq   = (const float*)d_in[11];
    const float* bq   = (const float*)d_in[12];
    const float* Wk   = (const float*)d_in[13];
    const float* bk   = (const float*)d_in[14];
    const float* Wv   = (const float*)d_in[15];
    const float* bv   = (const float*)d_in[16];
    const float* Wo   = (const float*)d_in[17];
    const float* bo   = (const float*)d_in[18];

    float* out = (float*)d_out;

    float *xg, *h1, *h2, *Q, *K, *V, *S, *att, *dump;
    cudaGetSymbolAddress((void**)&xg,  g_xg);
    cudaGetSymbolAddress((void**)&h1,  g_h1);
    cudaGetSymbolAddress((void**)&h2,  g_h2);
    cudaGetSymbolAddress((void**)&Q,   g_Q);
    cudaGetSymbolAddress((void**)&K,   g_K);
    cudaGetSymbolAddress((void**)&V,   g_V);
    cudaGetSymbolAddress((void**)&S,   g_S);
    cudaGetSymbolAddress((void**)&att, g_att);
    cudaGetSymbolAddress((void**)&dump, g_dump);

    // h_n / c_n destinations (appended after `out` if the buffer has room)
    const int OUT_ELEMS = MM * HH;            // 4194304
    float* hn_base;
    float* cn_base;
    if (out_size >= OUT_ELEMS + 4 * BB * HH) {
        hn_base = out + OUT_ELEMS;
        cn_base = out + OUT_ELEMS + 2 * BB * HH;
    } else {
        hn_base = dump;
        cn_base = dump + BB * HH;
    }

    const dim3 g_xg_grid(G4 / 128, MM / 128, 1);
    const dim3 g_qkv(HH / 128, MM / 128, 1);
    const dim3 g_sc(TT / 128, TT / 128, BB);
    const dim3 g_av(HH / 128, TT / 128, BB);

    // layer 0
    sgemm_kernel<<<g_xg_grid, 256>>>(x, Wih0, xg, MM, G4, FIN, 0, 0, 0, bih0, bhh0, nullptr, 1);
    lstm_rec_kernel<<<128, 256>>>(xg, Whh0, h1, hn_base, cn_base);
    // layer 1
    sgemm_kernel<<<g_xg_grid, 256>>>(h1, Wih1, xg, MM, G4, HH, 0, 0, 0, bih1, bhh1, nullptr, 1);
    lstm_rec_kernel<<<128, 256>>>(xg, Whh1, h2, hn_base + BB * HH, cn_base + BB * HH);
    // Q, K, V
    sgemm_kernel<<<g_qkv, 256>>>(h2, Wq, Q, MM, HH, HH, 0, 0, 0, bq, nullptr, nullptr, 1);
    sgemm_kernel<<<g_qkv, 256>>>(h2, Wk, K, MM, HH, HH, 0, 0, 0, bk, nullptr, nullptr, 1);
    sgemm_kernel<<<g_qkv, 256>>>(h2, Wv, V, MM, HH, HH, 0, 0, 0, bv, nullptr, nullptr, 1);
    // scores = Q @ K^T (batched)
    sgemm_kernel<<<g_sc, 256>>>(Q, K, S, TT, TT, HH,
                                (long)TT * HH, (long)TT * HH, (long)TT * TT,
                                nullptr, nullptr, nullptr, 1);
    // softmax(scores/sqrt(H) * mod)
    softmax_mod_kernel<<<BB * TT, 256>>>(S, ar_w, ma_w);
    // attended = attn @ V (batched, NN)
    sgemm_kernel<<<g_av, 256>>>(S, V, att, TT, HH, TT,
                                (long)TT * TT, (long)TT * HH, (long)TT * HH,
                                nullptr, nullptr, nullptr, 0);
    // out = attended @ Wo^T + bo + lstm_out
    sgemm_kernel<<<g_qkv, 256>>>(att, Wo, out, MM, HH, HH, 0, 0, 0, bo, nullptr, h2, 1);
}

// round 5
// speedup vs baseline: 1.1376x; 1.1376x over previous
#include <cuda_runtime.h>
#include <cuda_bf16.h>
#include <cstdint>

// ---------------------------------------------------------------------------
// Problem constants
// ---------------------------------------------------------------------------
#define BB 16
#define TT 1024
#define FIN 128
#define HH 256
#define G4 1024            // 4*H
#define MM (BB*TT)         // 16384

typedef unsigned long long ull;

// ---------------------------------------------------------------------------
// Scratch (static device arrays; no dynamic allocation allowed)
// ---------------------------------------------------------------------------
__device__ float g_xg [MM * G4];      // gate preactivations (reused layer0/1)
__device__ float g_h1 [MM * HH];      // layer0 hidden sequence
__device__ float g_h2 [MM * HH];      // layer1 hidden sequence (lstm_out)
__device__ float g_Q  [MM * HH];
__device__ float g_K  [MM * HH];
__device__ float g_V  [MM * HH];
__device__ float g_S  [BB * TT * TT]; // attention scores / probs
__device__ float g_att[MM * HH];
__device__ float g_dump[4 * BB * HH]; // fallback sink for h_n/c_n

// ---------------------------------------------------------------------------
// Helpers
// ---------------------------------------------------------------------------
__device__ __forceinline__ uint32_t smem_u32(const void* p) {
    return (uint32_t)__cvta_generic_to_shared(p);
}
__device__ __forceinline__ void st_cluster_f32(uint32_t saddr, int dst_rank, float v) {
    uint32_t r;
    asm volatile("mapa.shared::cluster.u32 %0, %1, %2;" : "=r"(r) : "r"(saddr), "r"(dst_rank));
    asm volatile("st.shared::cluster.f32 [%0], %1;" :: "r"(r), "f"(v) : "memory");
}
__device__ __forceinline__ void cluster_sync_all() {
    asm volatile("barrier.cluster.arrive.aligned;" ::: "memory");
    asm volatile("barrier.cluster.wait.aligned;" ::: "memory");
}
// MUFU-based activations (ex2 + rcp approx paths; ~1-2 ulp, no div.rn sequence)
__device__ __forceinline__ float fast_sigmoid(float x) {
    return __fdividef(1.f, 1.f + __expf(-x));
}
__device__ __forceinline__ float fast_tanh(float x) {
    float e = __expf(2.f * x);         // inf for large x is fine: 1 - 2/inf = 1
    return 1.f - __fdividef(2.f, e + 1.f);
}

// packed fp32x2 fma: d.lo += a.lo*b.lo ; d.hi += a.hi*b.hi
__device__ __forceinline__ void ffma2(ull& d, ull a, ull b) {
    asm("fma.rn.f32x2 %0, %1, %2, %0;" : "+l"(d) : "l"(a), "l"(b));
}
__device__ __forceinline__ void unpack2(ull v, float& lo, float& hi) {
    asm("mov.b64 {%0, %1}, %2;" : "=f"(lo), "=f"(hi) : "l"(v));
}

// cluster-scope mbarrier ops
__device__ __forceinline__ void mbar_init(uint32_t addr, uint32_t count) {
    asm volatile("mbarrier.init.shared.b64 [%0], %1;" :: "r"(addr), "r"(count) : "memory");
}
__device__ __forceinline__ void mbar_arrive_remote(uint32_t addr, uint32_t dst_rank) {
    asm volatile(
        "{\n\t"
        ".reg .b32 ra;\n\t"
        "mapa.shared::cluster.u32 ra, %0, %1;\n\t"
        "mbarrier.arrive.release.cluster.shared::cluster.b64 _, [ra];\n\t"
        "}"
        :: "r"(addr), "r"(dst_rank) : "memory");
}
__device__ __forceinline__ void mbar_wait_cluster(uint32_t addr, uint32_t parity) {
    asm volatile(
        "{\n\t"
        ".reg .pred P;\n\t"
        "WL_%=:\n\t"
        "mbarrier.try_wait.parity.acquire.cluster.shared::cta.b64 P, [%0], %1, 0x989680;\n\t"
        "@P bra.uni WD_%=;\n\t"
        "bra.uni WL_%=;\n\t"
        "WD_%=:\n\t"
        "}"
        :: "r"(addr), "r"(parity) : "memory");
}

// ---------------------------------------------------------------------------
// Persistent LSTM recurrence kernel.
// 16 clusters (batches) x 8 CTAs. Each CTA owns 32 hidden dims; Whh slice
// (128x256 fp32 = 128KB) lives in registers as f32x2 pairs.
// Per step: all warps GEMV (64 FFMA2/thread) + 8-lane shfl reduce ->
// __syncthreads -> warp0 computes activations + broadcasts h via DSMEM +
// posts 8 release-arrives -> ONLY WARP0 pays the cluster-scope acquire wait
// -> __syncthreads releases the other 7 warps (CTA-scope BAR: no cluster
// drain, no L1 flush per warp). Acquire->bar transitivity makes the remote
// DSMEM writes visible to all warps.
// Deadlock audit: warps 1-7 block at the trailing __syncthreads while warp 0
// waits on the mbarrier; they rendezvous at the same barrier -> no cycle.
// WAR audit: a CTA's step-t arrive follows its first __syncthreads of step t
// (all reads of rb(t) done); writers touch rb(t) again only in step t+1
// after collecting all 8 step-t arrivals.
// ---------------------------------------------------------------------------
__global__ void __cluster_dims__(8, 1, 1) __launch_bounds__(256, 1)
lstm_rec_kernel(const float* __restrict__ xg, const float* __restrict__ Whh,
                float* __restrict__ hseq, float* __restrict__ hn, float* __restrict__ cn)
{
    __shared__ float h_all[2][HH];
    __shared__ float gates_s[128];
    __shared__ __align__(8) ull mbar[1];

    const int tid   = threadIdx.x;
    const int rank  = blockIdx.x & 7;
    const int batch = blockIdx.x >> 3;
    const int u     = tid >> 3;   // 0..31 : output group (4 outputs, same gate)
    const int kc    = tid & 7;    // 0..7  : k-pair subset
    const int o0    = 4 * u;      // local output base

    // ---- load Whh slice into registers as f32x2 k-pairs ----
    ull w2[4][16];
    #pragma unroll
    for (int oo = 0; oo < 4; oo++) {
        const int o   = o0 + oo;
        const int row = ((o >> 5) << 8) + 32 * rank + (o & 31);
        const float* wr = Whh + (long)row * HH;
        #pragma unroll
        for (int j = 0; j < 16; j++) {
            float2 wp = *(const float2*)(wr + 2 * kc + 16 * j);
            ull v;
            asm("mov.b64 %0, {%1, %2};" : "=l"(v) : "f"(wp.x), "f"(wp.y));
            w2[oo][j] = v;
        }
    }

    h_all[0][tid] = 0.f;
    if (tid == 0) mbar_init(smem_u32(mbar), 8);

    float c_state = 0.f;
    uint32_t haddr[2] = {0, 0};
    if (tid < 32) {
        haddr[0] = smem_u32(&h_all[0][32 * rank + tid]);
        haddr[1] = smem_u32(&h_all[1][32 * rank + tid]);
    }
    const uint32_t mb = smem_u32(mbar);
    __syncthreads();
    cluster_sync_all();   // mbarrier + h0 visible cluster-wide

    const long xg_base = (long)batch * TT * G4;
    const int  xg_col  = ((o0 >> 5) << 8) + 32 * rank + (o0 & 31); // 4 consecutive cols

    // prefetch xg for t=0
    float4 xgv = make_float4(0.f, 0.f, 0.f, 0.f);
    if (kc == 0) xgv = *(const float4*)(xg + xg_base + xg_col);

    for (int t = 0; t < TT; t++) {
        const int rb = t & 1;
        const int wb = rb ^ 1;

        // GEMV over h_all[rb] : 64 FFMA2
        ull acc2[4] = {0ull, 0ull, 0ull, 0ull};
        const float* hrow = h_all[rb];
        #pragma unroll
        for (int j = 0; j < 16; j++) {
            ull h2 = *(const ull*)(hrow + 2 * kc + 16 * j);
            ffma2(acc2[0], w2[0][j], h2);
            ffma2(acc2[1], w2[1][j], h2);
            ffma2(acc2[2], w2[2][j], h2);
            ffma2(acc2[3], w2[3][j], h2);
        }
        float acc[4];
        #pragma unroll
        for (int g = 0; g < 4; g++) {
            float lo, hi;
            unpack2(acc2[g], lo, hi);
            acc[g] = lo + hi;
        }
        #pragma unroll
        for (int off = 4; off >= 1; off >>= 1) {
            acc[0] += __shfl_xor_sync(0xffffffffu, acc[0], off);
            acc[1] += __shfl_xor_sync(0xffffffffu, acc[1], off);
            acc[2] += __shfl_xor_sync(0xffffffffu, acc[2], off);
            acc[3] += __shfl_xor_sync(0xffffffffu, acc[3], off);
        }
        if (kc == 0) {
            *(float4*)&gates_s[o0] =
                make_float4(acc[0] + xgv.x, acc[1] + xgv.y, acc[2] + xgv.z, acc[3] + xgv.w);
        }
        __syncthreads();   // all warps done reading h_all[rb]; gates_s ready

        if (tid < 32) {    // warp 0 = writer warp
            const int hid = tid;
            float gi = gates_s[hid];
            float gf = gates_s[32 + hid];
            float gg = gates_s[64 + hid];
            float go = gates_s[96 + hid];
            float ig = fast_sigmoid(gi);
            float fg = fast_sigmoid(gf);
            float gt = fast_tanh(gg);
            float og = fast_sigmoid(go);
            c_state = fg * c_state + ig * gt;
            float h = og * fast_tanh(c_state);
            uint32_t dst = haddr[wb];
            #pragma unroll
            for (int d = 0; d < 8; d++) st_cluster_f32(dst, d, h);
            __syncwarp(0xffffffffu);   // all lanes' DSMEM stores done
            if (tid < 8) mbar_arrive_remote(mb, (uint32_t)tid);  // release-cluster
            // gmem stores AFTER the arrives (off the cluster critical path)
            hseq[((long)batch * TT + t) * HH + 32 * rank + hid] = h;
            if (t == TT - 1) {
                hn[batch * HH + 32 * rank + hid] = h;
                cn[batch * HH + 32 * rank + hid] = c_state;
            }
            // ONLY warp 0 pays the cluster-scope acquire wait
            mbar_wait_cluster(mb, (uint32_t)(t & 1));
        }

        // prefetch next xg row (independent; issued before the block barrier)
        if (kc == 0 && t + 1 < TT) {
            xgv = *(const float4*)(xg + xg_base + (long)(t + 1) * G4 + xg_col);
        }

        // cheap CTA-scope release of the other 7 warps; transitively orders
        // the remote h writes (acquired by warp 0) before everyone's reads
        __syncthreads();
    }
}

// ---------------------------------------------------------------------------
// SGEMM (proven R2 version): C[M,N] = A[M,K] @ B^T (b_nt=1, B is [N,K]) or
// A @ B (b_nt=0, B is [K,N]) + optional bias1[n] + bias2[n] + residual[m,n].
// Batched via gridDim.z with element strides sA/sB/sC. Tiles 128x128x8,
// 256 threads, 8x8 microtiles.
// ---------------------------------------------------------------------------
__global__ __launch_bounds__(256) void sgemm_kernel(
    const float* __restrict__ A, const float* __restrict__ B, float* __restrict__ C,
    int M, int N, int K,
    long sA, long sB, long sC,
    const float* __restrict__ bias1, const float* __restrict__ bias2,
    const float* __restrict__ res,
    int b_nt)
{
    __shared__ float As[8][132];
    __shared__ float Bs[8][132];

    const int bz = blockIdx.z;
    A += (long)bz * sA;
    B += (long)bz * sB;
    C += (long)bz * sC;

    const int bm = blockIdx.y * 128;
    const int bn = blockIdx.x * 128;
    const int tid = threadIdx.x;
    const int tx = tid & 15;
    const int ty = tid >> 4;

    float acc[8][8];
    #pragma unroll
    for (int i = 0; i < 8; i++)
        #pragma unroll
        for (int j = 0; j < 8; j++) acc[i][j] = 0.f;

    const int lr  = tid >> 1;        // 0..127
    const int lc4 = (tid & 1) * 4;   // 0 or 4
    const int kb  = tid >> 5;        // 0..7   (NN B load)
    const int nb  = (tid & 31) * 4;  // 0..124

    for (int k0 = 0; k0 < K; k0 += 8) {
        float4 a4 = *(const float4*)(A + (long)(bm + lr) * K + k0 + lc4);
        As[lc4 + 0][lr] = a4.x;
        As[lc4 + 1][lr] = a4.y;
        As[lc4 + 2][lr] = a4.z;
        As[lc4 + 3][lr] = a4.w;
        if (b_nt) {
            float4 b4 = *(const float4*)(B + (long)(bn + lr) * K + k0 + lc4);
            Bs[lc4 + 0][lr] = b4.x;
            Bs[lc4 + 1][lr] = b4.y;
            Bs[lc4 + 2][lr] = b4.z;
            Bs[lc4 + 3][lr] = b4.w;
        } else {
            float4 b4 = *(const float4*)(B + (long)(k0 + kb) * N + bn + nb);
            *(float4*)&Bs[kb][nb] = b4;
        }
        __syncthreads();

        #pragma unroll
        for (int kk = 0; kk < 8; kk++) {
            float a[8], b[8];
            *(float4*)&a[0] = *(const float4*)&As[kk][ty * 4];
            *(float4*)&a[4] = *(const float4*)&As[kk][64 + ty * 4];
            *(float4*)&b[0] = *(const float4*)&Bs[kk][tx * 4];
            *(float4*)&b[4] = *(const float4*)&Bs[kk][64 + tx * 4];
            #pragma unroll
            for (int i = 0; i < 8; i++)
                #pragma unroll
                for (int j = 0; j < 8; j++)
                    acc[i][j] = fmaf(a[i], b[j], acc[i][j]);
        }
        __syncthreads();
    }

    // epilogue
    #pragma unroll
    for (int ih = 0; ih < 2; ih++) {
        #pragma unroll
        for (int i = 0; i < 4; i++) {
            int m = bm + ih * 64 + ty * 4 + i;
            #pragma unroll
            for (int jh = 0; jh < 2; jh++) {
                int n = bn + jh * 64 + tx * 4;
                float4 v;
                v.x = acc[ih * 4 + i][jh * 4 + 0];
                v.y = acc[ih * 4 + i][jh * 4 + 1];
                v.z = acc[ih * 4 + i][jh * 4 + 2];
                v.w = acc[ih * 4 + i][jh * 4 + 3];
                if (bias1) {
                    const float4 b1 = *(const float4*)(bias1 + n);
                    v.x += b1.x; v.y += b1.y; v.z += b1.z; v.w += b1.w;
                }
                if (bias2) {
                    const float4 b2 = *(const float4*)(bias2 + n);
                    v.x += b2.x; v.y += b2.y; v.z += b2.z; v.w += b2.w;
                }
                if (res) {
                    const float4 r = *(const float4*)(res + (long)m * N + n);
                    v.x += r.x; v.y += r.y; v.z += r.z; v.w += r.w;
                }
                *(float4*)(C + (long)m * N + n) = v;
            }
        }
    }
}

// ---------------------------------------------------------------------------
// Softmax with ARMA modulation. One block (256 thr) per (b,q) row of 1024.
// mod depends only on d=|q-k| and is non-trivial only for d<=3.
// ---------------------------------------------------------------------------
__global__ __launch_bounds__(256) void softmax_mod_kernel(
    float* __restrict__ S, const float* __restrict__ ar_w, const float* __restrict__ ma_w)
{
    __shared__ float red[8];
    const int row = blockIdx.x;          // b*1024 + q
    const int q = row & (TT - 1);
    float* Sr = S + (long)row * TT;

    const float m0 = ma_w[0], m1 = ma_w[1];
    const float a0 = ar_w[0], a1 = ar_w[1], a2 = ar_w[2];
    const float mod0 = __expf(m0 + m1);
    const float mod1 = __expf(a0 + m0 + m1);
    const float mod2 = __expf(a1 + m1);
    const float mod3 = __expf(a2);

    const int t = threadIdx.x;
    float v[4];
    float mx = -1e30f;
    #pragma unroll
    for (int i = 0; i < 4; i++) {
        int k = t + 256 * i;
        float s = Sr[k] * 0.0625f;   // 1/sqrt(256)
        int d = ::abs(q - k);
        float md = (d > 3) ? 1.f : (d == 0 ? mod0 : (d == 1 ? mod1 : (d == 2 ? mod2 : mod3)));
        v[i] = s * md;
        mx = fmaxf(mx, v[i]);
    }
    #pragma unroll
    for (int off = 16; off; off >>= 1) mx = fmaxf(mx, __shfl_xor_sync(~0u, mx, off));
    if ((t & 31) == 0) red[t >> 5] = mx;
    __syncthreads();
    mx = red[0];
    #pragma unroll
    for (int w = 1; w < 8; w++) mx = fmaxf(mx, red[w]);

    float sum = 0.f;
    #pragma unroll
    for (int i = 0; i < 4; i++) { v[i] = __expf(v[i] - mx); sum += v[i]; }
    #pragma unroll
    for (int off = 16; off; off >>= 1) sum += __shfl_xor_sync(~0u, sum, off);
    __syncthreads();
    if ((t & 31) == 0) red[t >> 5] = sum;
    __syncthreads();
    sum = 0.f;
    #pragma unroll
    for (int w = 0; w < 8; w++) sum += red[w];
    const float inv = 1.f / sum;
    #pragma unroll
    for (int i = 0; i < 4; i++) Sr[t + 256 * i] = v[i] * inv;
}

// ---------------------------------------------------------------------------
// Launch
// ---------------------------------------------------------------------------
extern "C" void kernel_launch(void* const* d_in, const int* in_sizes, int n_in,
                              void* d_out, int out_size)
{
    const float* x    = (const float*)d_in[0];
    const float* Wih0 = (const float*)d_in[1];
    const float* Whh0 = (const float*)d_in[2];
    const float* bih0 = (const float*)d_in[3];
    const float* bhh0 = (const float*)d_in[4];
    const float* Wih1 = (const float*)d_in[5];
    const float* Whh1 = (const float*)d_in[6];
    const float* bih1 = (const float*)d_in[7];
    const float* bhh1 = (const float*)d_in[8];
    const float* ar_w = (const float*)d_in[9];
    const float* ma_w = (const float*)d_in[10];
    const float* Wq   = (const float*)d_in[11];
    const float* bq   = (const float*)d_in[12];
    const float* Wk   = (const float*)d_in[13];
    const float* bk   = (const float*)d_in[14];
    const float* Wv   = (const float*)d_in[15];
    const float* bv   = (const float*)d_in[16];
    const float* Wo   = (const float*)d_in[17];
    const float* bo   = (const float*)d_in[18];

    float* out = (float*)d_out;

    float *xg, *h1, *h2, *Q, *K, *V, *S, *att, *dump;
    cudaGetSymbolAddress((void**)&xg,  g_xg);
    cudaGetSymbolAddress((void**)&h1,  g_h1);
    cudaGetSymbolAddress((void**)&h2,  g_h2);
    cudaGetSymbolAddress((void**)&Q,   g_Q);
    cudaGetSymbolAddress((void**)&K,   g_K);
    cudaGetSymbolAddress((void**)&V,   g_V);
    cudaGetSymbolAddress((void**)&S,   g_S);
    cudaGetSymbolAddress((void**)&att, g_att);
    cudaGetSymbolAddress((void**)&dump, g_dump);

    // h_n / c_n destinations (appended after `out` if the buffer has room)
    const int OUT_ELEMS = MM * HH;            // 4194304
    float* hn_base;
    float* cn_base;
    if (out_size >= OUT_ELEMS + 4 * BB * HH) {
        hn_base = out + OUT_ELEMS;
        cn_base = out + OUT_ELEMS + 2 * BB * HH;
    } else {
        hn_base = dump;
        cn_base = dump + BB * HH;
    }

    const dim3 g_xg_grid(G4 / 128, MM / 128, 1);
    const dim3 g_qkv(HH / 128, MM / 128, 1);
    const dim3 g_sc(TT / 128, TT / 128, BB);
    const dim3 g_av(HH / 128, TT / 128, BB);

    // layer 0
    sgemm_kernel<<<g_xg_grid, 256>>>(x, Wih0, xg, MM, G4, FIN, 0, 0, 0, bih0, bhh0, nullptr, 1);
    lstm_rec_kernel<<<128, 256>>>(xg, Whh0, h1, hn_base, cn_base);
    // layer 1
    sgemm_kernel<<<g_xg_grid, 256>>>(h1, Wih1, xg, MM, G4, HH, 0, 0, 0, bih1, bhh1, nullptr, 1);
    lstm_rec_kernel<<<128, 256>>>(xg, Whh1, h2, hn_base + BB * HH, cn_base + BB * HH);
    // Q, K, V
    sgemm_kernel<<<g_qkv, 256>>>(h2, Wq, Q, MM, HH, HH, 0, 0, 0, bq, nullptr, nullptr, 1);
    sgemm_kernel<<<g_qkv, 256>>>(h2, Wk, K, MM, HH, HH, 0, 0, 0, bk, nullptr, nullptr, 1);
    sgemm_kernel<<<g_qkv, 256>>>(h2, Wv, V, MM, HH, HH, 0, 0, 0, bv, nullptr, nullptr, 1);
    // scores = Q @ K^T (batched)
    sgemm_kernel<<<g_sc, 256>>>(Q, K, S, TT, TT, HH,
                                (long)TT * HH, (long)TT * HH, (long)TT * TT,
                                nullptr, nullptr, nullptr, 1);
    // softmax(scores/sqrt(H) * mod)
    softmax_mod_kernel<<<BB * TT, 256>>>(S, ar_w, ma_w);
    // attended = attn @ V (batched, NN)
    sgemm_kernel<<<g_av, 256>>>(S, V, att, TT, HH, TT,
                                (long)TT * TT, (long)TT * HH, (long)TT * HH,
                                nullptr, nullptr, nullptr, 0);
    // out = attended @ Wo^T + bo + lstm_out
    sgemm_kernel<<<g_qkv, 256>>>(att, Wo, out, MM, HH, HH, 0, 0, 0, bo, nullptr, h2, 1);
}